// round 3
// baseline (speedup 1.0000x reference)
#include <cuda_runtime.h>
#include <cuda_bf16.h>

// Problem constants
#define B_    64
#define T_    1024
#define D_    512
#define H_    512
#define O_    128
#define HALF_ 256
#define M_    (B_ * T_)          // 65536 rows
#define BH_   (B_ * H_)          // 32768

// Scratch in device globals (no allocation allowed)
__device__ float g_d1[T_ * B_ * H_];    // [T,B,H]
__device__ float g_d2[T_ * B_ * H_];    // [T,B,H]
__device__ float g_mems[T_ * B_ * H_];  // [T,B,H]

// ---------------------------------------------------------------------------
// Packed fp32x2 helpers (sm_100+)
// ---------------------------------------------------------------------------
__device__ __forceinline__ unsigned long long fma2(unsigned long long a,
                                                   unsigned long long b,
                                                   unsigned long long c) {
    unsigned long long d;
    asm("fma.rn.f32x2 %0, %1, %2, %3;" : "=l"(d) : "l"(a), "l"(b), "l"(c));
    return d;
}
__device__ __forceinline__ float2 unpack2(unsigned long long v) {
    float2 f;
    asm("mov.b64 {%0, %1}, %2;" : "=f"(f.x), "=f"(f.y) : "l"(v));
    return f;
}

// ---------------------------------------------------------------------------
// 128x128 tile GEMM core. BK=8, 256 threads, 8x8 microtile per lane.
// Accumulators are f32x2 packed along M (pairs of adjacent m rows).
// A in smem as [stage][k][128] floats (m-major rows).
// B in smem DUPLICATED as [stage][k][128] float2 = (b,b) -> B frags load packed.
// Double-buffered: one __syncthreads per K-iteration.
// acc[mp][j]: mp = m-pair 0..3 (rows wm+2mp, wm+2mp+1), j = n offset 0..7.
// ---------------------------------------------------------------------------
struct SmemBuf {
    float  As[2][8][128];
    float2 Bs[2][8][128];
};

__device__ __forceinline__ void sgemm_core(
    const float* __restrict__ Aptr, int ALD, int AOFF, int m0,
    const float* __restrict__ Bptr, int BLD, int BOFF, int n0,
    int K, unsigned long long acc[4][8], SmemBuf* sb)
{
    const int tid  = threadIdx.x;
    const int grow = tid >> 1;            // 0..127
    const int gcol = (tid & 1) * 4;       // 0 or 4

    const float* ag = Aptr + (size_t)(m0 + grow) * ALD + AOFF + gcol;
    const float* bg = Bptr + (size_t)(n0 + grow) * BLD + BOFF + gcol;

    const int warp = tid >> 5, lane = tid & 31;
    const int wm = (warp & 1) * 64 + (lane & 7) * 8;   // multiple of 8
    const int wn = (warp >> 1) * 32 + (lane >> 3) * 8; // multiple of 8

    const int iters = K >> 3;

    // Prologue: fill stage 0
    {
        float4 pa = *(const float4*)ag;
        float4 pb = *(const float4*)bg;
        sb->As[0][gcol + 0][grow] = pa.x;
        sb->As[0][gcol + 1][grow] = pa.y;
        sb->As[0][gcol + 2][grow] = pa.z;
        sb->As[0][gcol + 3][grow] = pa.w;
        sb->Bs[0][gcol + 0][grow] = make_float2(pb.x, pb.x);
        sb->Bs[0][gcol + 1][grow] = make_float2(pb.y, pb.y);
        sb->Bs[0][gcol + 2][grow] = make_float2(pb.z, pb.z);
        sb->Bs[0][gcol + 3][grow] = make_float2(pb.w, pb.w);
    }
    __syncthreads();

    for (int kk = 0; kk < iters; ++kk) {
        const int s = kk & 1;

        float4 pa, pb;
        const bool more = (kk + 1 < iters);
        if (more) {
            pa = *(const float4*)(ag + (kk + 1) * 8);
            pb = *(const float4*)(bg + (kk + 1) * 8);
        }

        #pragma unroll
        for (int k = 0; k < 8; ++k) {
            // A fragment: 4 packed m-pairs (16B-aligned, two LDS.128)
            const ulonglong2* apv = (const ulonglong2*)&sb->As[s][k][wm];
            ulonglong2 a01 = apv[0];
            ulonglong2 a23 = apv[1];
            unsigned long long ap[4] = {a01.x, a01.y, a23.x, a23.y};
            // B fragment: 8 duplicated pairs (four LDS.128)
            const ulonglong2* bpv = (const ulonglong2*)&sb->Bs[s][k][wn];
            ulonglong2 b01 = bpv[0];
            ulonglong2 b23 = bpv[1];
            ulonglong2 b45 = bpv[2];
            ulonglong2 b67 = bpv[3];
            unsigned long long bp[8] = {b01.x, b01.y, b23.x, b23.y,
                                        b45.x, b45.y, b67.x, b67.y};
            #pragma unroll
            for (int mp = 0; mp < 4; ++mp)
                #pragma unroll
                for (int j = 0; j < 8; ++j)
                    acc[mp][j] = fma2(ap[mp], bp[j], acc[mp][j]);
        }

        if (more) {
            const int s2 = s ^ 1;
            sb->As[s2][gcol + 0][grow] = pa.x;
            sb->As[s2][gcol + 1][grow] = pa.y;
            sb->As[s2][gcol + 2][grow] = pa.z;
            sb->As[s2][gcol + 3][grow] = pa.w;
            sb->Bs[s2][gcol + 0][grow] = make_float2(pb.x, pb.x);
            sb->Bs[s2][gcol + 1][grow] = make_float2(pb.y, pb.y);
            sb->Bs[s2][gcol + 2][grow] = make_float2(pb.z, pb.z);
            sb->Bs[s2][gcol + 3][grow] = make_float2(pb.w, pb.w);
        }
        __syncthreads();
    }
}

__device__ __forceinline__ void zero_acc(unsigned long long acc[4][8]) {
    #pragma unroll
    for (int i = 0; i < 4; ++i)
        #pragma unroll
        for (int j = 0; j < 8; ++j)
            acc[i][j] = 0ull;
}

// Epilogue: write acc into [T,B,H] scratch (row m = b*T + t)
__device__ __forceinline__ void write_tbh(unsigned long long acc[4][8],
                                          float* __restrict__ dst,
                                          int m0, int n0)
{
    const int warp = threadIdx.x >> 5, lane = threadIdx.x & 31;
    const int wm = (warp & 1) * 64 + (lane & 7) * 8;
    const int wn = (warp >> 1) * 32 + (lane >> 3) * 8;
    #pragma unroll
    for (int mp = 0; mp < 4; ++mp) {
        float2 v[8];
        #pragma unroll
        for (int j = 0; j < 8; ++j) v[j] = unpack2(acc[mp][j]);
        #pragma unroll
        for (int p = 0; p < 2; ++p) {
            const int m = m0 + wm + 2 * mp + p;
            const int b = m >> 10;
            const int t = m & (T_ - 1);
            float* q = dst + (size_t)t * BH_ + (size_t)b * H_ + n0 + wn;
            if (p == 0) {
                *(float4*)q       = make_float4(v[0].x, v[1].x, v[2].x, v[3].x);
                *(float4*)(q + 4) = make_float4(v[4].x, v[5].x, v[6].x, v[7].x);
            } else {
                *(float4*)q       = make_float4(v[0].y, v[1].y, v[2].y, v[3].y);
                *(float4*)(q + 4) = make_float4(v[4].y, v[5].y, v[6].y, v[7].y);
            }
        }
    }
}

// ---------------------------------------------------------------------------
// Kernel 1: dual GEMM (two K-phases sharing one accumulator set).
// ---------------------------------------------------------------------------
__global__ __launch_bounds__(256, 2)
void dual_gemm_kernel(const float* __restrict__ x,
                      const float* __restrict__ w1,
                      const float* __restrict__ w2)
{
    __shared__ SmemBuf sb;

    const int m0 = blockIdx.x * 128;
    const int n0 = blockIdx.y * 128;

    unsigned long long acc[4][8];

    zero_acc(acc);
    sgemm_core(x, D_, 0, m0, w1, HALF_, 0, n0, HALF_, acc, &sb);
    write_tbh(acc, g_d1, m0, n0);

    __syncthreads();   // smem reuse fence between phases

    zero_acc(acc);
    sgemm_core(x, D_, HALF_, m0, w2, HALF_, 0, n0, HALF_, acc, &sb);
    write_tbh(acc, g_d2, m0, n0);
}

// ---------------------------------------------------------------------------
// Kernel 2: sequential EMA scan over T. One thread per (b,h).
// ---------------------------------------------------------------------------
__global__ __launch_bounds__(256)
void scan_kernel(const float* __restrict__ b1, const float* __restrict__ tau1,
                 const float* __restrict__ b2, const float* __restrict__ tau2)
{
    const int idx = blockIdx.x * blockDim.x + threadIdx.x;   // 0..32767
    const int h   = idx & (H_ - 1);

    const float a1 = 1.0f / (1.0f + __expf(-tau1[h]));
    const float a2 = 1.0f / (1.0f + __expf(-tau2[h]));
    const float c1 = 1.0f - a1;
    const float c2 = 1.0f - a2;
    const float bb1 = b1[h];
    const float bb2 = b2[h];

    float d1 = 0.0f, d2 = 0.0f, mem = 0.0f;

    #pragma unroll 1
    for (int t = 0; t < T_; t += 8) {
        float i1[8], i2[8];
        #pragma unroll
        for (int u = 0; u < 8; ++u) {
            i1[u] = g_d1[(size_t)(t + u) * BH_ + idx];
            i2[u] = g_d2[(size_t)(t + u) * BH_ + idx];
        }
        #pragma unroll
        for (int u = 0; u < 8; ++u) {
            d1  = a1 * d1 + c1 * (i1[u] + bb1);
            d2  = a2 * d2 + c2 * (i2[u] + bb2);
            mem = 0.8f * mem + 0.2f * (d1 + d2);
            g_mems[(size_t)(t + u) * BH_ + idx] = mem;
        }
    }
}

// ---------------------------------------------------------------------------
// Kernel 3: output GEMM + bias + sigmoid.
//   out[b,t,o] = sigmoid( sum_h mems[t,b,h] * wo[o,h] + bo[o] )
// Rows of mems: m = t*B + b.  Tile 128(M) x 128(N = full O).
// ---------------------------------------------------------------------------
__global__ __launch_bounds__(256, 2)
void out_gemm_kernel(const float* __restrict__ wo,
                     const float* __restrict__ bo,
                     float* __restrict__ out)
{
    __shared__ SmemBuf sb;

    const int m0 = blockIdx.x * 128;

    unsigned long long acc[4][8];
    zero_acc(acc);
    sgemm_core(g_mems, H_, 0, m0, wo, H_, 0, 0, H_, acc, &sb);

    const int warp = threadIdx.x >> 5, lane = threadIdx.x & 31;
    const int wm = (warp & 1) * 64 + (lane & 7) * 8;
    const int wn = (warp >> 1) * 32 + (lane >> 3) * 8;

    float4 bo0 = *(const float4*)(bo + wn);
    float4 bo1 = *(const float4*)(bo + wn + 4);
    const float bb[8] = {bo0.x, bo0.y, bo0.z, bo0.w, bo1.x, bo1.y, bo1.z, bo1.w};

    #pragma unroll
    for (int mp = 0; mp < 4; ++mp) {
        float2 v[8];
        #pragma unroll
        for (int j = 0; j < 8; ++j) v[j] = unpack2(acc[mp][j]);
        #pragma unroll
        for (int p = 0; p < 2; ++p) {
            const int m = m0 + wm + 2 * mp + p;
            const int t = m >> 6;          // / B_
            const int b = m & (B_ - 1);
            float r[8];
            #pragma unroll
            for (int j = 0; j < 8; ++j) {
                float val = ((p == 0) ? v[j].x : v[j].y) + bb[j];
                r[j] = 1.0f / (1.0f + __expf(-val));
            }
            float* q = out + (size_t)b * (T_ * O_) + (size_t)t * O_ + wn;
            *(float4*)q       = make_float4(r[0], r[1], r[2], r[3]);
            *(float4*)(q + 4) = make_float4(r[4], r[5], r[6], r[7]);
        }
    }
}

// ---------------------------------------------------------------------------
extern "C" void kernel_launch(void* const* d_in, const int* in_sizes, int n_in,
                              void* d_out, int out_size)
{
    const float* x    = (const float*)d_in[0];
    const float* w1   = (const float*)d_in[1];
    const float* b1   = (const float*)d_in[2];
    const float* tau1 = (const float*)d_in[3];
    const float* w2   = (const float*)d_in[4];
    const float* b2   = (const float*)d_in[5];
    const float* tau2 = (const float*)d_in[6];
    const float* wo   = (const float*)d_in[7];
    const float* bo   = (const float*)d_in[8];
    float* out = (float*)d_out;

    dim3 g1(M_ / 128, H_ / 128);          // 512 x 4
    dual_gemm_kernel<<<g1, 256>>>(x, w1, w2);

    scan_kernel<<<BH_ / 256, 256>>>(b1, tau1, b2, tau2);

    dim3 g3(M_ / 128, O_ / 128);          // 512 x 1
    out_gemm_kernel<<<g3, 256>>>(wo, bo, out);
}

// round 5
// speedup vs baseline: 2.5290x; 2.5290x over previous
#include <cuda_runtime.h>
#include <cuda_bf16.h>
#include <cstdint>

// Problem constants
#define B_    64
#define T_    1024
#define D_    512
#define H_    512
#define O_    128
#define HALF_ 256
#define M_    (B_ * T_)          // 65536
#define BH_   (B_ * H_)          // 32768

// ---------------------------------------------------------------------------
// Device-global scratch (no allocation allowed)
// ---------------------------------------------------------------------------
__device__ float          g_d1[T_ * B_ * H_];     // [T,B,H] fp32
__device__ float          g_d2[T_ * B_ * H_];     // [T,B,H] fp32
__device__ __nv_bfloat16  g_xh[M_ * D_];
__device__ __nv_bfloat16  g_xl[M_ * D_];
__device__ __nv_bfloat16  g_w1h[H_ * HALF_], g_w1l[H_ * HALF_];
__device__ __nv_bfloat16  g_w2h[H_ * HALF_], g_w2l[H_ * HALF_];
__device__ __nv_bfloat16  g_woh[O_ * H_],    g_wol[O_ * H_];
__device__ __nv_bfloat16  g_mh[T_ * B_ * H_];     // mems hi, row m = t*B+b
__device__ __nv_bfloat16  g_ml[T_ * B_ * H_];

// ---------------------------------------------------------------------------
// Helpers
// ---------------------------------------------------------------------------
__device__ __forceinline__ uint32_t smem_u32(const void* p) {
    uint32_t a;
    asm("{ .reg .u64 t; cvta.to.shared.u64 t, %1; cvt.u32.u64 %0, t; }"
        : "=r"(a) : "l"(p));
    return a;
}
__device__ __forceinline__ void ldsm4(uint32_t r[4], uint32_t addr) {
    asm volatile("ldmatrix.sync.aligned.m8n8.x4.shared.b16 {%0,%1,%2,%3}, [%4];"
        : "=r"(r[0]), "=r"(r[1]), "=r"(r[2]), "=r"(r[3]) : "r"(addr));
}
__device__ __forceinline__ void mma16816(float c[4], const uint32_t a[4],
                                         const uint32_t b0, const uint32_t b1) {
    asm volatile(
        "mma.sync.aligned.m16n8k16.row.col.f32.bf16.bf16.f32 "
        "{%0,%1,%2,%3}, {%4,%5,%6,%7}, {%8,%9}, {%0,%1,%2,%3};"
        : "+f"(c[0]), "+f"(c[1]), "+f"(c[2]), "+f"(c[3])
        : "r"(a[0]), "r"(a[1]), "r"(a[2]), "r"(a[3]), "r"(b0), "r"(b1));
}

// Tile geometry: 128 rows x 64 bf16 cols = 128B/row, SW128, 16 KB
#define TILE_BYTES 16384
#define SW128(o)   ((o) ^ (((o) >> 3) & 0x70))

// Load one 128x64 bf16 tile (K-major global) into swizzled smem. 256 threads.
__device__ __forceinline__ void load_tile(char* s, const __nv_bfloat16* __restrict__ g,
                                          int ld, int row0, int k0)
{
    const int tid = threadIdx.x;
    #pragma unroll
    for (int i = 0; i < 4; ++i) {
        const int slot = tid + i * 256;      // 0..1023
        const int r = slot >> 3;
        const int v = slot & 7;
        uint4 d = *(const uint4*)(g + (size_t)(row0 + r) * ld + k0 + v * 8);
        const uint32_t bo = (uint32_t)(r * 128 + v * 16);
        *(uint4*)(s + SW128(bo)) = d;
    }
}

// ---------------------------------------------------------------------------
// 3-term bf16 HMMA chunk: acc += Ah*Wh + Al*Wh + Ah*Wl over K=64.
// Warp tile 32(m) x 64(n). acc[mt][nt][4], mt<2 (16m each), nt<8 (8n each).
// ---------------------------------------------------------------------------
__device__ __forceinline__ void gemm_chunk_3term(
    uint32_t sAh, uint32_t sAl, uint32_t sWh, uint32_t sWl,
    int warp_m, int warp_n, int lane, float acc[2][8][4])
{
    #pragma unroll
    for (int ks = 0; ks < 4; ++ks) {
        // A fragments: lanes 0-15 rows m0..15 @k, lanes 16-31 same rows @k+8
        const int akb = ks * 32 + ((lane & 16) ? 16 : 0);
        uint32_t ah[2][4], al[2][4];
        #pragma unroll
        for (int mt = 0; mt < 2; ++mt) {
            const int row = warp_m + mt * 16 + (lane & 15);
            const uint32_t off = SW128((uint32_t)(row * 128 + akb));
            ldsm4(ah[mt], sAh + off);
            ldsm4(al[mt], sAl + off);
        }
        // B fragments: x4 covers two n8 tiles (n16).
        // lanes 0-7: n0..7 @k ; 8-15: n0..7 @k+8 ; 16-23: n8..15 @k ; 24-31: n8..15 @k+8
        const int bkb = ks * 32 + ((lane & 8) ? 16 : 0);
        #pragma unroll
        for (int nt2 = 0; nt2 < 4; ++nt2) {
            const int brow = warp_n + nt2 * 16 + (lane & 7) + ((lane & 16) ? 8 : 0);
            const uint32_t boff = SW128((uint32_t)(brow * 128 + bkb));
            uint32_t wh[4], wl[4];
            ldsm4(wh, sWh + boff);
            ldsm4(wl, sWl + boff);
            #pragma unroll
            for (int mt = 0; mt < 2; ++mt) {
                mma16816(acc[mt][nt2 * 2 + 0], ah[mt], wh[0], wh[1]);
                mma16816(acc[mt][nt2 * 2 + 1], ah[mt], wh[2], wh[3]);
                mma16816(acc[mt][nt2 * 2 + 0], al[mt], wh[0], wh[1]);
                mma16816(acc[mt][nt2 * 2 + 1], al[mt], wh[2], wh[3]);
                mma16816(acc[mt][nt2 * 2 + 0], ah[mt], wl[0], wl[1]);
                mma16816(acc[mt][nt2 * 2 + 1], ah[mt], wl[2], wl[3]);
            }
        }
    }
}

// ---------------------------------------------------------------------------
// split fp32 -> bf16 hi/lo planes
// ---------------------------------------------------------------------------
__global__ void split_kernel(const float* __restrict__ src,
                             __nv_bfloat16* __restrict__ hi,
                             __nv_bfloat16* __restrict__ lo, int nvec)
{
    for (int i = blockIdx.x * blockDim.x + threadIdx.x; i < nvec;
         i += gridDim.x * blockDim.x) {
        float4 v = ((const float4*)src)[i];
        float f[4] = {v.x, v.y, v.z, v.w};
        uint32_t ph[2], pl[2];
        #pragma unroll
        for (int j = 0; j < 2; ++j) {
            __nv_bfloat16 h0 = __float2bfloat16(f[2*j]);
            __nv_bfloat16 h1 = __float2bfloat16(f[2*j+1]);
            __nv_bfloat16 l0 = __float2bfloat16(f[2*j]   - __bfloat162float(h0));
            __nv_bfloat16 l1 = __float2bfloat16(f[2*j+1] - __bfloat162float(h1));
            ph[j] = (uint32_t)__bfloat16_as_ushort(h0) | ((uint32_t)__bfloat16_as_ushort(h1) << 16);
            pl[j] = (uint32_t)__bfloat16_as_ushort(l0) | ((uint32_t)__bfloat16_as_ushort(l1) << 16);
        }
        ((uint2*)hi)[i] = make_uint2(ph[0], ph[1]);
        ((uint2*)lo)[i] = make_uint2(pl[0], pl[1]);
    }
}

#define SMEM_GEMM (1024 + 4 * TILE_BYTES)

// ---------------------------------------------------------------------------
// GEMM-1: d1/d2 = x-halves @ w1/w2^T (bf16x3 HMMA). Grid (512, 4), 256 thr.
// ---------------------------------------------------------------------------
__global__ __launch_bounds__(256, 2)
void hmma_gemm1_kernel()
{
    extern __shared__ __align__(16) char smraw[];
    char* smem = smraw + ((1024 - (smem_u32(smraw) & 1023)) & 1023);
    char* sAh = smem;
    char* sAl = smem + TILE_BYTES;
    char* sWh = smem + 2 * TILE_BYTES;
    char* sWl = smem + 3 * TILE_BYTES;
    const uint32_t uAh = smem_u32(sAh), uAl = smem_u32(sAl);
    const uint32_t uWh = smem_u32(sWh), uWl = smem_u32(sWl);

    const int tid    = threadIdx.x;
    const int wid    = tid >> 5;
    const int lane   = tid & 31;
    const int warp_m = (wid & 3) * 32;
    const int warp_n = (wid >> 2) * 64;

    const int m0 = blockIdx.x * 128;
    const int n0 = blockIdx.y * 128;

    #pragma unroll 1
    for (int phase = 0; phase < 2; ++phase) {
        const __nv_bfloat16* wh = phase ? g_w2h : g_w1h;
        const __nv_bfloat16* wl = phase ? g_w2l : g_w1l;
        const int akbase = phase * HALF_;
        float acc[2][8][4];
        #pragma unroll
        for (int a = 0; a < 2; ++a)
            #pragma unroll
            for (int b = 0; b < 8; ++b)
                #pragma unroll
                for (int c = 0; c < 4; ++c) acc[a][b][c] = 0.0f;

        #pragma unroll 1
        for (int c = 0; c < 4; ++c) {
            load_tile(sAh, g_xh, D_,    m0, akbase + c * 64);
            load_tile(sAl, g_xl, D_,    m0, akbase + c * 64);
            load_tile(sWh, wh,   HALF_, n0, c * 64);
            load_tile(sWl, wl,   HALF_, n0, c * 64);
            __syncthreads();
            gemm_chunk_3term(uAh, uAl, uWh, uWl, warp_m, warp_n, lane, acc);
            __syncthreads();
        }

        // Epilogue -> g_d1/g_d2 [T,B,H], row m = b*T + t
        float* dst = phase ? g_d2 : g_d1;
        #pragma unroll
        for (int mt = 0; mt < 2; ++mt) {
            #pragma unroll
            for (int half = 0; half < 2; ++half) {
                const int m = m0 + warp_m + mt * 16 + (lane >> 2) + half * 8;
                const int b = m >> 10;
                const int t = m & (T_ - 1);
                float* rowp = dst + (size_t)t * BH_ + (size_t)b * H_ + n0 + warp_n;
                #pragma unroll
                for (int nt = 0; nt < 8; ++nt) {
                    const int n = nt * 8 + (lane & 3) * 2;
                    float2 v = half ? make_float2(acc[mt][nt][2], acc[mt][nt][3])
                                    : make_float2(acc[mt][nt][0], acc[mt][nt][1]);
                    *(float2*)(rowp + n) = v;
                }
            }
        }
    }
}

// ---------------------------------------------------------------------------
// Scan: sequential EMA over T; emits mems as bf16 hi/lo split.
// ---------------------------------------------------------------------------
__global__ __launch_bounds__(256)
void scan_kernel(const float* __restrict__ b1, const float* __restrict__ tau1,
                 const float* __restrict__ b2, const float* __restrict__ tau2)
{
    const int idx = blockIdx.x * blockDim.x + threadIdx.x;   // 0..32767
    const int h   = idx & (H_ - 1);

    const float a1 = 1.0f / (1.0f + __expf(-tau1[h]));
    const float a2 = 1.0f / (1.0f + __expf(-tau2[h]));
    const float c1 = 1.0f - a1;
    const float c2 = 1.0f - a2;
    const float bb1 = b1[h];
    const float bb2 = b2[h];

    float d1 = 0.0f, d2 = 0.0f, mem = 0.0f;

    #pragma unroll 1
    for (int t = 0; t < T_; t += 8) {
        float i1[8], i2[8];
        #pragma unroll
        for (int u = 0; u < 8; ++u) {
            i1[u] = g_d1[(size_t)(t + u) * BH_ + idx];
            i2[u] = g_d2[(size_t)(t + u) * BH_ + idx];
        }
        #pragma unroll
        for (int u = 0; u < 8; ++u) {
            d1  = a1 * d1 + c1 * (i1[u] + bb1);
            d2  = a2 * d2 + c2 * (i2[u] + bb2);
            mem = 0.8f * mem + 0.2f * (d1 + d2);
            const size_t off = (size_t)(t + u) * BH_ + idx;
            __nv_bfloat16 mh = __float2bfloat16(mem);
            __nv_bfloat16 ml = __float2bfloat16(mem - __bfloat162float(mh));
            g_mh[off] = mh;
            g_ml[off] = ml;
        }
    }
}

// ---------------------------------------------------------------------------
// GEMM-2: out = sigmoid(mems @ wo^T + bo). Grid (512), N = 128 = full O, K=512.
// ---------------------------------------------------------------------------
__global__ __launch_bounds__(256, 2)
void hmma_gemm2_kernel(const float* __restrict__ bo, float* __restrict__ out)
{
    extern __shared__ __align__(16) char smraw[];
    char* smem = smraw + ((1024 - (smem_u32(smraw) & 1023)) & 1023);
    char* sAh = smem;
    char* sAl = smem + TILE_BYTES;
    char* sWh = smem + 2 * TILE_BYTES;
    char* sWl = smem + 3 * TILE_BYTES;
    const uint32_t uAh = smem_u32(sAh), uAl = smem_u32(sAl);
    const uint32_t uWh = smem_u32(sWh), uWl = smem_u32(sWl);

    const int tid    = threadIdx.x;
    const int wid    = tid >> 5;
    const int lane   = tid & 31;
    const int warp_m = (wid & 3) * 32;
    const int warp_n = (wid >> 2) * 64;

    const int m0 = blockIdx.x * 128;

    float acc[2][8][4];
    #pragma unroll
    for (int a = 0; a < 2; ++a)
        #pragma unroll
        for (int b = 0; b < 8; ++b)
            #pragma unroll
            for (int c = 0; c < 4; ++c) acc[a][b][c] = 0.0f;

    #pragma unroll 1
    for (int c = 0; c < 8; ++c) {
        load_tile(sAh, g_mh,  H_, m0, c * 64);
        load_tile(sAl, g_ml,  H_, m0, c * 64);
        load_tile(sWh, g_woh, H_, 0,  c * 64);
        load_tile(sWl, g_wol, H_, 0,  c * 64);
        __syncthreads();
        gemm_chunk_3term(uAh, uAl, uWh, uWl, warp_m, warp_n, lane, acc);
        __syncthreads();
    }

    // Epilogue: bias + sigmoid; out[b,t,o], row m = t*B + b
    #pragma unroll
    for (int mt = 0; mt < 2; ++mt) {
        #pragma unroll
        for (int half = 0; half < 2; ++half) {
            const int m = m0 + warp_m + mt * 16 + (lane >> 2) + half * 8;
            const int t = m >> 6;           // / B_
            const int b = m & (B_ - 1);
            float* rowp = out + (size_t)b * (T_ * O_) + (size_t)t * O_ + warp_n;
            #pragma unroll
            for (int nt = 0; nt < 8; ++nt) {
                const int n = nt * 8 + (lane & 3) * 2;
                float v0 = half ? acc[mt][nt][2] : acc[mt][nt][0];
                float v1 = half ? acc[mt][nt][3] : acc[mt][nt][1];
                v0 += bo[warp_n + n];
                v1 += bo[warp_n + n + 1];
                v0 = 1.0f / (1.0f + __expf(-v0));
                v1 = 1.0f / (1.0f + __expf(-v1));
                *(float2*)(rowp + n) = make_float2(v0, v1);
            }
        }
    }
}

// ---------------------------------------------------------------------------
extern "C" void kernel_launch(void* const* d_in, const int* in_sizes, int n_in,
                              void* d_out, int out_size)
{
    const float* x    = (const float*)d_in[0];
    const float* w1   = (const float*)d_in[1];
    const float* b1   = (const float*)d_in[2];
    const float* tau1 = (const float*)d_in[3];
    const float* w2   = (const float*)d_in[4];
    const float* b2   = (const float*)d_in[5];
    const float* tau2 = (const float*)d_in[6];
    const float* wo   = (const float*)d_in[7];
    const float* bo   = (const float*)d_in[8];
    float* out = (float*)d_out;

    cudaFuncSetAttribute(hmma_gemm1_kernel,
                         cudaFuncAttributeMaxDynamicSharedMemorySize, SMEM_GEMM);
    cudaFuncSetAttribute(hmma_gemm2_kernel,
                         cudaFuncAttributeMaxDynamicSharedMemorySize, SMEM_GEMM);

    __nv_bfloat16 *xh, *xl, *w1h, *w1l, *w2h, *w2l, *woh, *wol;
    cudaGetSymbolAddress((void**)&xh,  g_xh);
    cudaGetSymbolAddress((void**)&xl,  g_xl);
    cudaGetSymbolAddress((void**)&w1h, g_w1h);
    cudaGetSymbolAddress((void**)&w1l, g_w1l);
    cudaGetSymbolAddress((void**)&w2h, g_w2h);
    cudaGetSymbolAddress((void**)&w2l, g_w2l);
    cudaGetSymbolAddress((void**)&woh, g_woh);
    cudaGetSymbolAddress((void**)&wol, g_wol);

    // Split conversions
    {
        int nv = (M_ * D_) / 4;
        split_kernel<<<(nv + 255) / 256, 256>>>(x, xh, xl, nv);
        nv = (H_ * HALF_) / 4;
        split_kernel<<<(nv + 255) / 256, 256>>>(w1, w1h, w1l, nv);
        split_kernel<<<(nv + 255) / 256, 256>>>(w2, w2h, w2l, nv);
        nv = (O_ * H_) / 4;
        split_kernel<<<(nv + 255) / 256, 256>>>(wo, woh, wol, nv);
    }

    dim3 g1(M_ / 128, H_ / 128);          // 512 x 4
    hmma_gemm1_kernel<<<g1, 256, SMEM_GEMM>>>();

    scan_kernel<<<BH_ / 256, 256>>>(b1, tau1, b2, tau2);

    hmma_gemm2_kernel<<<M_ / 128, 256, SMEM_GEMM>>>(bo, out);
}

// round 6
// speedup vs baseline: 2.6368x; 1.0426x over previous
#include <cuda_runtime.h>
#include <cuda_bf16.h>
#include <cstdint>

// Problem constants
#define B_    64
#define T_    1024
#define D_    512
#define H_    512
#define O_    128
#define HALF_ 256
#define M_    (B_ * T_)          // 65536
#define BH_   (B_ * H_)          // 32768

// ---------------------------------------------------------------------------
// Device-global scratch
// ---------------------------------------------------------------------------
__device__ float          g_d1[T_ * B_ * H_];     // [T,B,H] fp32
__device__ float          g_d2[T_ * B_ * H_];     // [T,B,H] fp32
__device__ __nv_bfloat16  g_w1h[H_ * HALF_], g_w1l[H_ * HALF_];
__device__ __nv_bfloat16  g_w2h[H_ * HALF_], g_w2l[H_ * HALF_];
__device__ __nv_bfloat16  g_woh[O_ * H_],    g_wol[O_ * H_];
__device__ __nv_bfloat16  g_mh[T_ * B_ * H_];     // mems hi, row m = t*B+b
__device__ __nv_bfloat16  g_ml[T_ * B_ * H_];

// ---------------------------------------------------------------------------
// Helpers
// ---------------------------------------------------------------------------
__device__ __forceinline__ uint32_t smem_u32(const void* p) {
    uint32_t a;
    asm("{ .reg .u64 t; cvta.to.shared.u64 t, %1; cvt.u32.u64 %0, t; }"
        : "=r"(a) : "l"(p));
    return a;
}
__device__ __forceinline__ void ldsm4(uint32_t r[4], uint32_t addr) {
    asm volatile("ldmatrix.sync.aligned.m8n8.x4.shared.b16 {%0,%1,%2,%3}, [%4];"
        : "=r"(r[0]), "=r"(r[1]), "=r"(r[2]), "=r"(r[3]) : "r"(addr));
}
__device__ __forceinline__ void mma16816(float c[4], const uint32_t a[4],
                                         const uint32_t b0, const uint32_t b1) {
    asm volatile(
        "mma.sync.aligned.m16n8k16.row.col.f32.bf16.bf16.f32 "
        "{%0,%1,%2,%3}, {%4,%5,%6,%7}, {%8,%9}, {%0,%1,%2,%3};"
        : "+f"(c[0]), "+f"(c[1]), "+f"(c[2]), "+f"(c[3])
        : "r"(a[0]), "r"(a[1]), "r"(a[2]), "r"(a[3]), "r"(b0), "r"(b1));
}
__device__ __forceinline__ void cp16(uint32_t dst, const void* src) {
    asm volatile("cp.async.cg.shared.global [%0], [%1], 16;"
        :: "r"(dst), "l"(src) : "memory");
}
#define CP_COMMIT() asm volatile("cp.async.commit_group;" ::: "memory")
#define CP_WAIT0()  asm volatile("cp.async.wait_group 0;" ::: "memory")

// Tile geometry: 128 rows x 64 bf16 cols = 128B/row, SW128, 16 KB
#define TILE_BYTES 16384
#define SW128(o)   ((o) ^ (((o) >> 3) & 0x70))

// cp.async one 128x64 bf16 tile (K-major global) into swizzled smem. 512 thr.
__device__ __forceinline__ void cp_tile(uint32_t sbase,
                                        const __nv_bfloat16* __restrict__ g,
                                        int ld, int row0, int k0, int tid)
{
    #pragma unroll
    for (int i = 0; i < 2; ++i) {
        const int slot = tid + i * 512;      // 0..1023
        const int r = slot >> 3;
        const int v = slot & 7;
        cp16(sbase + SW128((uint32_t)(r * 128 + v * 16)),
             g + (size_t)(row0 + r) * ld + k0 + v * 8);
    }
}

// LDG a 128x64 fp32 A-chunk into registers (4 x float4 per thread, 512 thr)
__device__ __forceinline__ void ldg_x(float4 xf[4], const float* __restrict__ x,
                                      int m0, int k0, int tid)
{
    #pragma unroll
    for (int i = 0; i < 4; ++i) {
        const int slot = tid + i * 512;      // 0..2047
        const int r = slot >> 4;             // 0..127
        const int v = slot & 15;             // float4 index within 64 cols
        xf[i] = *(const float4*)(x + (size_t)(m0 + r) * D_ + k0 + v * 4);
    }
}

// Split registers to bf16 hi/lo and store into swizzled smem tiles
__device__ __forceinline__ void sts_x(const float4 xf[4], char* sAh, char* sAl,
                                      int tid)
{
    #pragma unroll
    for (int i = 0; i < 4; ++i) {
        const int slot = tid + i * 512;
        const int r = slot >> 4;
        const int v = slot & 15;
        const uint32_t off = SW128((uint32_t)(r * 128 + v * 8));
        const float f[4] = {xf[i].x, xf[i].y, xf[i].z, xf[i].w};
        uint32_t ph[2], pl[2];
        #pragma unroll
        for (int j = 0; j < 2; ++j) {
            __nv_bfloat16 h0 = __float2bfloat16(f[2*j]);
            __nv_bfloat16 h1 = __float2bfloat16(f[2*j+1]);
            __nv_bfloat16 l0 = __float2bfloat16(f[2*j]   - __bfloat162float(h0));
            __nv_bfloat16 l1 = __float2bfloat16(f[2*j+1] - __bfloat162float(h1));
            ph[j] = (uint32_t)__bfloat16_as_ushort(h0) | ((uint32_t)__bfloat16_as_ushort(h1) << 16);
            pl[j] = (uint32_t)__bfloat16_as_ushort(l0) | ((uint32_t)__bfloat16_as_ushort(l1) << 16);
        }
        *(uint2*)(sAh + off) = make_uint2(ph[0], ph[1]);
        *(uint2*)(sAl + off) = make_uint2(pl[0], pl[1]);
    }
}

// ---------------------------------------------------------------------------
// 3-term bf16 HMMA chunk: acc += Ah*Wh + Al*Wh + Ah*Wl over K=64.
// Warp tile 32(m) x 32(n). acc[mt][nt][4], mt<2 (16m), nt<4 (8n).
// ---------------------------------------------------------------------------
__device__ __forceinline__ void gemm_chunk_3term(
    uint32_t sAh, uint32_t sAl, uint32_t sWh, uint32_t sWl,
    int warp_m, int warp_n, int lane, float acc[2][4][4])
{
    #pragma unroll
    for (int ks = 0; ks < 4; ++ks) {
        const int akb = ks * 32 + ((lane & 16) ? 16 : 0);
        uint32_t ah[2][4], al[2][4];
        #pragma unroll
        for (int mt = 0; mt < 2; ++mt) {
            const int row = warp_m + mt * 16 + (lane & 15);
            const uint32_t off = SW128((uint32_t)(row * 128 + akb));
            ldsm4(ah[mt], sAh + off);
            ldsm4(al[mt], sAl + off);
        }
        const int bkb = ks * 32 + ((lane & 8) ? 16 : 0);
        #pragma unroll
        for (int nt2 = 0; nt2 < 2; ++nt2) {
            const int brow = warp_n + nt2 * 16 + (lane & 7) + ((lane & 16) ? 8 : 0);
            const uint32_t boff = SW128((uint32_t)(brow * 128 + bkb));
            uint32_t wh[4], wl[4];
            ldsm4(wh, sWh + boff);
            ldsm4(wl, sWl + boff);
            #pragma unroll
            for (int mt = 0; mt < 2; ++mt) {
                mma16816(acc[mt][nt2 * 2 + 0], ah[mt], wh[0], wh[1]);
                mma16816(acc[mt][nt2 * 2 + 1], ah[mt], wh[2], wh[3]);
                mma16816(acc[mt][nt2 * 2 + 0], al[mt], wh[0], wh[1]);
                mma16816(acc[mt][nt2 * 2 + 1], al[mt], wh[2], wh[3]);
                mma16816(acc[mt][nt2 * 2 + 0], ah[mt], wl[0], wl[1]);
                mma16816(acc[mt][nt2 * 2 + 1], ah[mt], wl[2], wl[3]);
            }
        }
    }
}

// ---------------------------------------------------------------------------
// split fp32 -> bf16 hi/lo planes (weights only; x split fused into gemm1)
// ---------------------------------------------------------------------------
__global__ void split_kernel(const float* __restrict__ src,
                             __nv_bfloat16* __restrict__ hi,
                             __nv_bfloat16* __restrict__ lo, int nvec)
{
    for (int i = blockIdx.x * blockDim.x + threadIdx.x; i < nvec;
         i += gridDim.x * blockDim.x) {
        float4 v = ((const float4*)src)[i];
        float f[4] = {v.x, v.y, v.z, v.w};
        uint32_t ph[2], pl[2];
        #pragma unroll
        for (int j = 0; j < 2; ++j) {
            __nv_bfloat16 h0 = __float2bfloat16(f[2*j]);
            __nv_bfloat16 h1 = __float2bfloat16(f[2*j+1]);
            __nv_bfloat16 l0 = __float2bfloat16(f[2*j]   - __bfloat162float(h0));
            __nv_bfloat16 l1 = __float2bfloat16(f[2*j+1] - __bfloat162float(h1));
            ph[j] = (uint32_t)__bfloat16_as_ushort(h0) | ((uint32_t)__bfloat16_as_ushort(h1) << 16);
            pl[j] = (uint32_t)__bfloat16_as_ushort(l0) | ((uint32_t)__bfloat16_as_ushort(l1) << 16);
        }
        ((uint2*)hi)[i] = make_uint2(ph[0], ph[1]);
        ((uint2*)lo)[i] = make_uint2(pl[0], pl[1]);
    }
}

// Stage layout: per stage Ah|Al|Wh|Wl (4 x 16 KB = 64 KB); 2 stages = 128 KB.
#define STAGE_BYTES (4 * TILE_BYTES)
#define SMEM_GEMM   (1024 + 2 * STAGE_BYTES)

// ---------------------------------------------------------------------------
// GEMM-1: d1/d2 = x-halves @ w1/w2^T. Fused x split. Grid (512, 4), 512 thr.
// ---------------------------------------------------------------------------
__global__ __launch_bounds__(512)
void hmma_gemm1_kernel(const float* __restrict__ x)
{
    extern __shared__ __align__(16) char smraw[];
    char* smem = smraw + ((1024 - (smem_u32(smraw) & 1023)) & 1023);
    const uint32_t sbase = smem_u32(smem);

    const int tid    = threadIdx.x;
    const int wid    = tid >> 5;
    const int lane   = tid & 31;
    const int warp_m = (wid & 3) * 32;
    const int warp_n = (wid >> 2) * 32;

    const int m0 = blockIdx.x * 128;
    const int n0 = blockIdx.y * 128;

    #pragma unroll 1
    for (int phase = 0; phase < 2; ++phase) {
        const __nv_bfloat16* wh = phase ? g_w2h : g_w1h;
        const __nv_bfloat16* wl = phase ? g_w2l : g_w1l;
        const int akbase = phase * HALF_;

        float acc[2][4][4];
        #pragma unroll
        for (int a = 0; a < 2; ++a)
            #pragma unroll
            for (int b = 0; b < 4; ++b)
                #pragma unroll
                for (int c = 0; c < 4; ++c) acc[a][b][c] = 0.0f;

        // Prologue: fill stage 0
        {
            float4 xf[4];
            ldg_x(xf, x, m0, akbase, tid);
            cp_tile(sbase + 2 * TILE_BYTES, wh, HALF_, n0, 0, tid);
            cp_tile(sbase + 3 * TILE_BYTES, wl, HALF_, n0, 0, tid);
            CP_COMMIT();
            sts_x(xf, smem, smem + TILE_BYTES, tid);
        }

        #pragma unroll 1
        for (int c = 0; c < 4; ++c) {
            const int s = c & 1;
            const uint32_t sb  = sbase + s * STAGE_BYTES;
            const uint32_t sb2 = sbase + (s ^ 1) * STAGE_BYTES;
            char* pb2 = smem + (s ^ 1) * STAGE_BYTES;
            const bool more = (c < 3);

            float4 xf[4];
            if (more) ldg_x(xf, x, m0, akbase + (c + 1) * 64, tid);

            CP_WAIT0();
            __syncthreads();

            if (more) {
                cp_tile(sb2 + 2 * TILE_BYTES, wh, HALF_, n0, (c + 1) * 64, tid);
                cp_tile(sb2 + 3 * TILE_BYTES, wl, HALF_, n0, (c + 1) * 64, tid);
                CP_COMMIT();
            }

            gemm_chunk_3term(sb, sb + TILE_BYTES,
                             sb + 2 * TILE_BYTES, sb + 3 * TILE_BYTES,
                             warp_m, warp_n, lane, acc);

            if (more) sts_x(xf, pb2, pb2 + TILE_BYTES, tid);
        }
        __syncthreads();

        // Epilogue -> g_d1/g_d2 [T,B,H], row m = b*T + t
        float* dst = phase ? g_d2 : g_d1;
        #pragma unroll
        for (int mt = 0; mt < 2; ++mt) {
            #pragma unroll
            for (int half = 0; half < 2; ++half) {
                const int m = m0 + warp_m + mt * 16 + (lane >> 2) + half * 8;
                const int b = m >> 10;
                const int t = m & (T_ - 1);
                float* rowp = dst + (size_t)t * BH_ + (size_t)b * H_ + n0 + warp_n;
                #pragma unroll
                for (int nt = 0; nt < 4; ++nt) {
                    const int n = nt * 8 + (lane & 3) * 2;
                    float2 v = half ? make_float2(acc[mt][nt][2], acc[mt][nt][3])
                                    : make_float2(acc[mt][nt][0], acc[mt][nt][1]);
                    *(float2*)(rowp + n) = v;
                }
            }
        }
    }
}

// ---------------------------------------------------------------------------
// Scan: sequential EMA over T; emits mems as bf16 hi/lo split.
// ---------------------------------------------------------------------------
__global__ __launch_bounds__(256)
void scan_kernel(const float* __restrict__ b1, const float* __restrict__ tau1,
                 const float* __restrict__ b2, const float* __restrict__ tau2)
{
    const int idx = blockIdx.x * blockDim.x + threadIdx.x;   // 0..32767
    const int h   = idx & (H_ - 1);

    const float a1 = 1.0f / (1.0f + __expf(-tau1[h]));
    const float a2 = 1.0f / (1.0f + __expf(-tau2[h]));
    const float c1 = 1.0f - a1;
    const float c2 = 1.0f - a2;
    const float bb1 = b1[h];
    const float bb2 = b2[h];

    float d1 = 0.0f, d2 = 0.0f, mem = 0.0f;

    #pragma unroll 1
    for (int t = 0; t < T_; t += 8) {
        float i1[8], i2[8];
        #pragma unroll
        for (int u = 0; u < 8; ++u) {
            i1[u] = g_d1[(size_t)(t + u) * BH_ + idx];
            i2[u] = g_d2[(size_t)(t + u) * BH_ + idx];
        }
        #pragma unroll
        for (int u = 0; u < 8; ++u) {
            d1  = a1 * d1 + c1 * (i1[u] + bb1);
            d2  = a2 * d2 + c2 * (i2[u] + bb2);
            mem = 0.8f * mem + 0.2f * (d1 + d2);
            const size_t off = (size_t)(t + u) * BH_ + idx;
            __nv_bfloat16 mh = __float2bfloat16(mem);
            __nv_bfloat16 ml = __float2bfloat16(mem - __bfloat162float(mh));
            g_mh[off] = mh;
            g_ml[off] = ml;
        }
    }
}

// ---------------------------------------------------------------------------
// GEMM-2: out = sigmoid(mems @ wo^T + bo). Grid (512), 512 thr, K = 512.
// ---------------------------------------------------------------------------
__global__ __launch_bounds__(512)
void hmma_gemm2_kernel(const float* __restrict__ bo, float* __restrict__ out)
{
    extern __shared__ __align__(16) char smraw[];
    char* smem = smraw + ((1024 - (smem_u32(smraw) & 1023)) & 1023);
    const uint32_t sbase = smem_u32(smem);

    const int tid    = threadIdx.x;
    const int wid    = tid >> 5;
    const int lane   = tid & 31;
    const int warp_m = (wid & 3) * 32;
    const int warp_n = (wid >> 2) * 32;

    const int m0 = blockIdx.x * 128;

    float acc[2][4][4];
    #pragma unroll
    for (int a = 0; a < 2; ++a)
        #pragma unroll
        for (int b = 0; b < 4; ++b)
            #pragma unroll
            for (int c = 0; c < 4; ++c) acc[a][b][c] = 0.0f;

    // Prologue: stage 0
    cp_tile(sbase,                  g_mh,  H_, m0, 0, tid);
    cp_tile(sbase + TILE_BYTES,     g_ml,  H_, m0, 0, tid);
    cp_tile(sbase + 2 * TILE_BYTES, g_woh, H_, 0,  0, tid);
    cp_tile(sbase + 3 * TILE_BYTES, g_wol, H_, 0,  0, tid);
    CP_COMMIT();

    #pragma unroll 1
    for (int c = 0; c < 8; ++c) {
        const int s = c & 1;
        const uint32_t sb  = sbase + s * STAGE_BYTES;
        const uint32_t sb2 = sbase + (s ^ 1) * STAGE_BYTES;
        const bool more = (c < 7);

        CP_WAIT0();
        __syncthreads();

        if (more) {
            const int k1 = (c + 1) * 64;
            cp_tile(sb2,                  g_mh,  H_, m0, k1, tid);
            cp_tile(sb2 + TILE_BYTES,     g_ml,  H_, m0, k1, tid);
            cp_tile(sb2 + 2 * TILE_BYTES, g_woh, H_, 0,  k1, tid);
            cp_tile(sb2 + 3 * TILE_BYTES, g_wol, H_, 0,  k1, tid);
            CP_COMMIT();
        }

        gemm_chunk_3term(sb, sb + TILE_BYTES,
                         sb + 2 * TILE_BYTES, sb + 3 * TILE_BYTES,
                         warp_m, warp_n, lane, acc);
    }

    // Epilogue: bias + sigmoid; out[b,t,o], row m = t*B + b
    #pragma unroll
    for (int mt = 0; mt < 2; ++mt) {
        #pragma unroll
        for (int half = 0; half < 2; ++half) {
            const int m = m0 + warp_m + mt * 16 + (lane >> 2) + half * 8;
            const int t = m >> 6;           // / B_
            const int b = m & (B_ - 1);
            float* rowp = out + (size_t)b * (T_ * O_) + (size_t)t * O_ + warp_n;
            #pragma unroll
            for (int nt = 0; nt < 4; ++nt) {
                const int n = nt * 8 + (lane & 3) * 2;
                float v0 = half ? acc[mt][nt][2] : acc[mt][nt][0];
                float v1 = half ? acc[mt][nt][3] : acc[mt][nt][1];
                v0 += bo[warp_n + n];
                v1 += bo[warp_n + n + 1];
                v0 = 1.0f / (1.0f + __expf(-v0));
                v1 = 1.0f / (1.0f + __expf(-v1));
                *(float2*)(rowp + n) = make_float2(v0, v1);
            }
        }
    }
}

// ---------------------------------------------------------------------------
extern "C" void kernel_launch(void* const* d_in, const int* in_sizes, int n_in,
                              void* d_out, int out_size)
{
    const float* x    = (const float*)d_in[0];
    const float* w1   = (const float*)d_in[1];
    const float* b1   = (const float*)d_in[2];
    const float* tau1 = (const float*)d_in[3];
    const float* w2   = (const float*)d_in[4];
    const float* b2   = (const float*)d_in[5];
    const float* tau2 = (const float*)d_in[6];
    const float* wo   = (const float*)d_in[7];
    const float* bo   = (const float*)d_in[8];
    float* out = (float*)d_out;

    cudaFuncSetAttribute(hmma_gemm1_kernel,
                         cudaFuncAttributeMaxDynamicSharedMemorySize, SMEM_GEMM);
    cudaFuncSetAttribute(hmma_gemm2_kernel,
                         cudaFuncAttributeMaxDynamicSharedMemorySize, SMEM_GEMM);

    __nv_bfloat16 *w1h, *w1l, *w2h, *w2l, *woh, *wol;
    cudaGetSymbolAddress((void**)&w1h, g_w1h);
    cudaGetSymbolAddress((void**)&w1l, g_w1l);
    cudaGetSymbolAddress((void**)&w2h, g_w2h);
    cudaGetSymbolAddress((void**)&w2l, g_w2l);
    cudaGetSymbolAddress((void**)&woh, g_woh);
    cudaGetSymbolAddress((void**)&wol, g_wol);

    // Weight splits (x split is fused into gemm1)
    {
        int nv = (H_ * HALF_) / 4;
        split_kernel<<<(nv + 255) / 256, 256>>>(w1, w1h, w1l, nv);
        split_kernel<<<(nv + 255) / 256, 256>>>(w2, w2h, w2l, nv);
        nv = (O_ * H_) / 4;
        split_kernel<<<(nv + 255) / 256, 256>>>(wo, woh, wol, nv);
    }

    dim3 g1(M_ / 128, H_ / 128);          // 512 x 4
    hmma_gemm1_kernel<<<g1, 512, SMEM_GEMM>>>(x);

    scan_kernel<<<BH_ / 256, 256>>>(b1, tau1, b2, tau2);

    hmma_gemm2_kernel<<<M_ / 128, 512, SMEM_GEMM>>>(bo, out);
}

// round 7
// speedup vs baseline: 2.8715x; 1.0890x over previous
#include <cuda_runtime.h>
#include <cuda_bf16.h>
#include <cstdint>

// Problem constants
#define B_    64
#define T_    1024
#define D_    512
#define H_    512
#define O_    128
#define HALF_ 256
#define M_    (B_ * T_)          // 65536
#define BH_   (B_ * H_)          // 32768

// ---------------------------------------------------------------------------
// Device-global scratch
// ---------------------------------------------------------------------------
__device__ float          g_d1[T_ * B_ * H_];     // [T,B,H] fp32
__device__ float          g_d2[T_ * B_ * H_];     // [T,B,H] fp32
__device__ __nv_bfloat16  g_xh[M_ * D_];          // x split hi
__device__ __nv_bfloat16  g_xl[M_ * D_];          // x split lo
__device__ __nv_bfloat16  g_w1h[H_ * HALF_], g_w1l[H_ * HALF_];
__device__ __nv_bfloat16  g_w2h[H_ * HALF_], g_w2l[H_ * HALF_];
__device__ __nv_bfloat16  g_woh[O_ * H_],    g_wol[O_ * H_];
__device__ __nv_bfloat16  g_mh[T_ * B_ * H_];     // mems hi, row m = t*B+b
__device__ __nv_bfloat16  g_ml[T_ * B_ * H_];

// ---------------------------------------------------------------------------
// Helpers
// ---------------------------------------------------------------------------
__device__ __forceinline__ uint32_t smem_u32(const void* p) {
    uint32_t a;
    asm("{ .reg .u64 t; cvta.to.shared.u64 t, %1; cvt.u32.u64 %0, t; }"
        : "=r"(a) : "l"(p));
    return a;
}
__device__ __forceinline__ void ldsm4(uint32_t r[4], uint32_t addr) {
    asm volatile("ldmatrix.sync.aligned.m8n8.x4.shared.b16 {%0,%1,%2,%3}, [%4];"
        : "=r"(r[0]), "=r"(r[1]), "=r"(r[2]), "=r"(r[3]) : "r"(addr));
}
__device__ __forceinline__ void mma16816(float c[4], const uint32_t a[4],
                                         const uint32_t b0, const uint32_t b1) {
    asm volatile(
        "mma.sync.aligned.m16n8k16.row.col.f32.bf16.bf16.f32 "
        "{%0,%1,%2,%3}, {%4,%5,%6,%7}, {%8,%9}, {%0,%1,%2,%3};"
        : "+f"(c[0]), "+f"(c[1]), "+f"(c[2]), "+f"(c[3])
        : "r"(a[0]), "r"(a[1]), "r"(a[2]), "r"(a[3]), "r"(b0), "r"(b1));
}
__device__ __forceinline__ void cp16(uint32_t dst, const void* src) {
    asm volatile("cp.async.cg.shared.global [%0], [%1], 16;"
        :: "r"(dst), "l"(src) : "memory");
}
#define CP_COMMIT() asm volatile("cp.async.commit_group;" ::: "memory")
#define CP_WAIT0()  asm volatile("cp.async.wait_group 0;" ::: "memory")
#define CP_WAIT1()  asm volatile("cp.async.wait_group 1;" ::: "memory")

#define TILE_BYTES 16384                  // 128 rows x 128 B
#define SW128(o)   ((o) ^ (((o) >> 3) & 0x70))

// cp.async an R x 64 bf16 tile (K-major global) into swizzled smem. 512 thr.
template <int R>
__device__ __forceinline__ void cp_tile(uint32_t sbase,
                                        const __nv_bfloat16* __restrict__ g,
                                        int ld, int row0, int k0, int tid)
{
    #pragma unroll
    for (int i = 0; i < (R * 8) / 512; ++i) {
        const int slot = tid + i * 512;
        const int r = slot >> 3;
        const int v = slot & 7;
        cp16(sbase + SW128((uint32_t)(r * 128 + v * 16)),
             g + (size_t)(row0 + r) * ld + k0 + v * 8);
    }
}

// ---------------------------------------------------------------------------
// split fp32 -> bf16 hi/lo planes
// ---------------------------------------------------------------------------
__global__ void split_kernel(const float* __restrict__ src,
                             __nv_bfloat16* __restrict__ hi,
                             __nv_bfloat16* __restrict__ lo, int nvec)
{
    for (int i = blockIdx.x * blockDim.x + threadIdx.x; i < nvec;
         i += gridDim.x * blockDim.x) {
        float4 v = ((const float4*)src)[i];
        float f[4] = {v.x, v.y, v.z, v.w};
        uint32_t ph[2], pl[2];
        #pragma unroll
        for (int j = 0; j < 2; ++j) {
            __nv_bfloat16 h0 = __float2bfloat16(f[2*j]);
            __nv_bfloat16 h1 = __float2bfloat16(f[2*j+1]);
            __nv_bfloat16 l0 = __float2bfloat16(f[2*j]   - __bfloat162float(h0));
            __nv_bfloat16 l1 = __float2bfloat16(f[2*j+1] - __bfloat162float(h1));
            ph[j] = (uint32_t)__bfloat16_as_ushort(h0) | ((uint32_t)__bfloat16_as_ushort(h1) << 16);
            pl[j] = (uint32_t)__bfloat16_as_ushort(l0) | ((uint32_t)__bfloat16_as_ushort(l1) << 16);
        }
        ((uint2*)hi)[i] = make_uint2(ph[0], ph[1]);
        ((uint2*)lo)[i] = make_uint2(pl[0], pl[1]);
    }
}

// ---------------------------------------------------------------------------
// GEMM-1: CTA tile 128(m) x 256(n), K-chunks of 64, 512 thr, 16 warps 4m x 4n,
// warp tile 32 x 64. Continuous 8-chunk cp.async pipeline (phase 0: chunks
// 0-3 with w1, phase 1: chunks 4-7 with w2). Stage: Ah|Al (16K) Wh|Wl (32K).
// ---------------------------------------------------------------------------
#define G1_A_BYTES  TILE_BYTES            // 128 x 64 bf16
#define G1_W_BYTES  (2 * TILE_BYTES)      // 256 x 64 bf16
#define G1_STAGE    (2 * G1_A_BYTES + 2 * G1_W_BYTES)   // 96 KB
#define SMEM_G1     (1024 + 2 * G1_STAGE)               // 193 KB

__global__ __launch_bounds__(512)
void hmma_gemm1_kernel()
{
    extern __shared__ __align__(16) char smraw[];
    char* smem = smraw + ((1024 - (smem_u32(smraw) & 1023)) & 1023);
    const uint32_t sbase = smem_u32(smem);

    const int tid    = threadIdx.x;
    const int wid    = tid >> 5;
    const int lane   = tid & 31;
    const int warp_m = (wid & 3) * 32;
    const int warp_n = (wid >> 2) * 64;

    const int m0 = blockIdx.x * 128;
    const int n0 = blockIdx.y * 256;

    // Stage offsets
    #define G1_OFF_AH 0
    #define G1_OFF_AL G1_A_BYTES
    #define G1_OFF_WH (2 * G1_A_BYTES)
    #define G1_OFF_WL (2 * G1_A_BYTES + G1_W_BYTES)

    auto issue_chunk = [&](int c, uint32_t sb) {
        const __nv_bfloat16* wh = (c >= 4) ? g_w2h : g_w1h;
        const __nv_bfloat16* wl = (c >= 4) ? g_w2l : g_w1l;
        const int kx = c * 64;             // x column
        const int kw = (c & 3) * 64;       // w column
        cp_tile<128>(sb + G1_OFF_AH, g_xh, D_,    m0, kx, tid);
        cp_tile<128>(sb + G1_OFF_AL, g_xl, D_,    m0, kx, tid);
        cp_tile<256>(sb + G1_OFF_WH, wh,   HALF_, n0, kw, tid);
        cp_tile<256>(sb + G1_OFF_WL, wl,   HALF_, n0, kw, tid);
        CP_COMMIT();
    };

    float acc[2][8][4];
    #pragma unroll
    for (int a = 0; a < 2; ++a)
        #pragma unroll
        for (int b = 0; b < 8; ++b)
            #pragma unroll
            for (int cc = 0; cc < 4; ++cc) acc[a][b][cc] = 0.0f;

    issue_chunk(0, sbase);

    #pragma unroll 1
    for (int c = 0; c < 8; ++c) {
        const uint32_t sb = sbase + (c & 1) * G1_STAGE;

        if (c + 1 < 8) {
            issue_chunk(c + 1, sbase + ((c + 1) & 1) * G1_STAGE);
            CP_WAIT1();
        } else {
            CP_WAIT0();
        }
        __syncthreads();

        // Compute chunk c: 3-term bf16 HMMA over K=64
        const uint32_t sAh = sb + G1_OFF_AH, sAl = sb + G1_OFF_AL;
        const uint32_t sWh = sb + G1_OFF_WH, sWl = sb + G1_OFF_WL;
        #pragma unroll
        for (int ks = 0; ks < 4; ++ks) {
            const int akb = ks * 32 + ((lane & 16) ? 16 : 0);
            uint32_t ah[2][4], al[2][4];
            #pragma unroll
            for (int mt = 0; mt < 2; ++mt) {
                const int row = warp_m + mt * 16 + (lane & 15);
                const uint32_t off = SW128((uint32_t)(row * 128 + akb));
                ldsm4(ah[mt], sAh + off);
                ldsm4(al[mt], sAl + off);
            }
            const int bkb = ks * 32 + ((lane & 8) ? 16 : 0);
            #pragma unroll
            for (int nt2 = 0; nt2 < 4; ++nt2) {
                const int brow = warp_n + nt2 * 16 + (lane & 7) + ((lane & 16) ? 8 : 0);
                const uint32_t boff = SW128((uint32_t)(brow * 128 + bkb));
                uint32_t wh[4], wl[4];
                ldsm4(wh, sWh + boff);
                ldsm4(wl, sWl + boff);
                #pragma unroll
                for (int mt = 0; mt < 2; ++mt) {
                    mma16816(acc[mt][nt2 * 2 + 0], ah[mt], wh[0], wh[1]);
                    mma16816(acc[mt][nt2 * 2 + 1], ah[mt], wh[2], wh[3]);
                    mma16816(acc[mt][nt2 * 2 + 0], al[mt], wh[0], wh[1]);
                    mma16816(acc[mt][nt2 * 2 + 1], al[mt], wh[2], wh[3]);
                    mma16816(acc[mt][nt2 * 2 + 0], ah[mt], wl[0], wl[1]);
                    mma16816(acc[mt][nt2 * 2 + 1], ah[mt], wl[2], wl[3]);
                }
            }
        }
        __syncthreads();

        if (c == 3 || c == 7) {
            // Epilogue: write phase result, reset accumulators
            float* dst = (c == 3) ? g_d1 : g_d2;
            #pragma unroll
            for (int mt = 0; mt < 2; ++mt) {
                #pragma unroll
                for (int half = 0; half < 2; ++half) {
                    const int m = m0 + warp_m + mt * 16 + (lane >> 2) + half * 8;
                    const int b = m >> 10;
                    const int t = m & (T_ - 1);
                    float* rowp = dst + (size_t)t * BH_ + (size_t)b * H_ + n0 + warp_n;
                    #pragma unroll
                    for (int nt = 0; nt < 8; ++nt) {
                        const int n = nt * 8 + (lane & 3) * 2;
                        float2 v = half ? make_float2(acc[mt][nt][2], acc[mt][nt][3])
                                        : make_float2(acc[mt][nt][0], acc[mt][nt][1]);
                        *(float2*)(rowp + n) = v;
                    }
                }
            }
            #pragma unroll
            for (int a = 0; a < 2; ++a)
                #pragma unroll
                for (int b = 0; b < 8; ++b)
                    #pragma unroll
                    for (int cc = 0; cc < 4; ++cc) acc[a][b][cc] = 0.0f;
        }
    }
}

// ---------------------------------------------------------------------------
// Scan: sequential EMA over T; emits mems as bf16 hi/lo split.
// ---------------------------------------------------------------------------
__global__ __launch_bounds__(256)
void scan_kernel(const float* __restrict__ b1, const float* __restrict__ tau1,
                 const float* __restrict__ b2, const float* __restrict__ tau2)
{
    const int idx = blockIdx.x * blockDim.x + threadIdx.x;   // 0..32767
    const int h   = idx & (H_ - 1);

    const float a1 = 1.0f / (1.0f + __expf(-tau1[h]));
    const float a2 = 1.0f / (1.0f + __expf(-tau2[h]));
    const float c1 = 1.0f - a1;
    const float c2 = 1.0f - a2;
    const float bb1 = b1[h];
    const float bb2 = b2[h];

    float d1 = 0.0f, d2 = 0.0f, mem = 0.0f;

    #pragma unroll 1
    for (int t = 0; t < T_; t += 8) {
        float i1[8], i2[8];
        #pragma unroll
        for (int u = 0; u < 8; ++u) {
            i1[u] = g_d1[(size_t)(t + u) * BH_ + idx];
            i2[u] = g_d2[(size_t)(t + u) * BH_ + idx];
        }
        #pragma unroll
        for (int u = 0; u < 8; ++u) {
            d1  = a1 * d1 + c1 * (i1[u] + bb1);
            d2  = a2 * d2 + c2 * (i2[u] + bb2);
            mem = 0.8f * mem + 0.2f * (d1 + d2);
            const size_t off = (size_t)(t + u) * BH_ + idx;
            __nv_bfloat16 mh = __float2bfloat16(mem);
            __nv_bfloat16 ml = __float2bfloat16(mem - __bfloat162float(mh));
            g_mh[off] = mh;
            g_ml[off] = ml;
        }
    }
}

// ---------------------------------------------------------------------------
// GEMM-2: out = sigmoid(mems @ wo^T + bo). Grid (512), 512 thr, K = 512.
// CTA tile 128 x 128, warp 32 x 32, 2-stage cp.async.
// ---------------------------------------------------------------------------
#define G2_STAGE (4 * TILE_BYTES)
#define SMEM_G2  (1024 + 2 * G2_STAGE)

__global__ __launch_bounds__(512)
void hmma_gemm2_kernel(const float* __restrict__ bo, float* __restrict__ out)
{
    extern __shared__ __align__(16) char smraw[];
    char* smem = smraw + ((1024 - (smem_u32(smraw) & 1023)) & 1023);
    const uint32_t sbase = smem_u32(smem);

    const int tid    = threadIdx.x;
    const int wid    = tid >> 5;
    const int lane   = tid & 31;
    const int warp_m = (wid & 3) * 32;
    const int warp_n = (wid >> 2) * 32;

    const int m0 = blockIdx.x * 128;

    float acc[2][4][4];
    #pragma unroll
    for (int a = 0; a < 2; ++a)
        #pragma unroll
        for (int b = 0; b < 4; ++b)
            #pragma unroll
            for (int c = 0; c < 4; ++c) acc[a][b][c] = 0.0f;

    auto issue_chunk = [&](int c, uint32_t sb) {
        const int k1 = c * 64;
        cp_tile<128>(sb,                  g_mh,  H_, m0, k1, tid);
        cp_tile<128>(sb + TILE_BYTES,     g_ml,  H_, m0, k1, tid);
        cp_tile<128>(sb + 2 * TILE_BYTES, g_woh, H_, 0,  k1, tid);
        cp_tile<128>(sb + 3 * TILE_BYTES, g_wol, H_, 0,  k1, tid);
        CP_COMMIT();
    };

    issue_chunk(0, sbase);

    #pragma unroll 1
    for (int c = 0; c < 8; ++c) {
        const uint32_t sb = sbase + (c & 1) * G2_STAGE;

        if (c + 1 < 8) {
            issue_chunk(c + 1, sbase + ((c + 1) & 1) * G2_STAGE);
            CP_WAIT1();
        } else {
            CP_WAIT0();
        }
        __syncthreads();

        const uint32_t sAh = sb, sAl = sb + TILE_BYTES;
        const uint32_t sWh = sb + 2 * TILE_BYTES, sWl = sb + 3 * TILE_BYTES;
        #pragma unroll
        for (int ks = 0; ks < 4; ++ks) {
            const int akb = ks * 32 + ((lane & 16) ? 16 : 0);
            uint32_t ah[2][4], al[2][4];
            #pragma unroll
            for (int mt = 0; mt < 2; ++mt) {
                const int row = warp_m + mt * 16 + (lane & 15);
                const uint32_t off = SW128((uint32_t)(row * 128 + akb));
                ldsm4(ah[mt], sAh + off);
                ldsm4(al[mt], sAl + off);
            }
            const int bkb = ks * 32 + ((lane & 8) ? 16 : 0);
            #pragma unroll
            for (int nt2 = 0; nt2 < 2; ++nt2) {
                const int brow = warp_n + nt2 * 16 + (lane & 7) + ((lane & 16) ? 8 : 0);
                const uint32_t boff = SW128((uint32_t)(brow * 128 + bkb));
                uint32_t wh[4], wl[4];
                ldsm4(wh, sWh + boff);
                ldsm4(wl, sWl + boff);
                #pragma unroll
                for (int mt = 0; mt < 2; ++mt) {
                    mma16816(acc[mt][nt2 * 2 + 0], ah[mt], wh[0], wh[1]);
                    mma16816(acc[mt][nt2 * 2 + 1], ah[mt], wh[2], wh[3]);
                    mma16816(acc[mt][nt2 * 2 + 0], al[mt], wh[0], wh[1]);
                    mma16816(acc[mt][nt2 * 2 + 1], al[mt], wh[2], wh[3]);
                    mma16816(acc[mt][nt2 * 2 + 0], ah[mt], wl[0], wl[1]);
                    mma16816(acc[mt][nt2 * 2 + 1], ah[mt], wl[2], wl[3]);
                }
            }
        }
        __syncthreads();
    }

    // Epilogue: bias + sigmoid; out[b,t,o], row m = t*B + b
    #pragma unroll
    for (int mt = 0; mt < 2; ++mt) {
        #pragma unroll
        for (int half = 0; half < 2; ++half) {
            const int m = m0 + warp_m + mt * 16 + (lane >> 2) + half * 8;
            const int t = m >> 6;           // / B_
            const int b = m & (B_ - 1);
            float* rowp = out + (size_t)b * (T_ * O_) + (size_t)t * O_ + warp_n;
            #pragma unroll
            for (int nt = 0; nt < 4; ++nt) {
                const int n = nt * 8 + (lane & 3) * 2;
                float v0 = half ? acc[mt][nt][2] : acc[mt][nt][0];
                float v1 = half ? acc[mt][nt][3] : acc[mt][nt][1];
                v0 += bo[warp_n + n];
                v1 += bo[warp_n + n + 1];
                v0 = 1.0f / (1.0f + __expf(-v0));
                v1 = 1.0f / (1.0f + __expf(-v1));
                *(float2*)(rowp + n) = make_float2(v0, v1);
            }
        }
    }
}

// ---------------------------------------------------------------------------
extern "C" void kernel_launch(void* const* d_in, const int* in_sizes, int n_in,
                              void* d_out, int out_size)
{
    const float* x    = (const float*)d_in[0];
    const float* w1   = (const float*)d_in[1];
    const float* b1   = (const float*)d_in[2];
    const float* tau1 = (const float*)d_in[3];
    const float* w2   = (const float*)d_in[4];
    const float* b2   = (const float*)d_in[5];
    const float* tau2 = (const float*)d_in[6];
    const float* wo   = (const float*)d_in[7];
    const float* bo   = (const float*)d_in[8];
    float* out = (float*)d_out;

    cudaFuncSetAttribute(hmma_gemm1_kernel,
                         cudaFuncAttributeMaxDynamicSharedMemorySize, SMEM_G1);
    cudaFuncSetAttribute(hmma_gemm2_kernel,
                         cudaFuncAttributeMaxDynamicSharedMemorySize, SMEM_G2);

    __nv_bfloat16 *xh, *xl, *w1h, *w1l, *w2h, *w2l, *woh, *wol;
    cudaGetSymbolAddress((void**)&xh,  g_xh);
    cudaGetSymbolAddress((void**)&xl,  g_xl);
    cudaGetSymbolAddress((void**)&w1h, g_w1h);
    cudaGetSymbolAddress((void**)&w1l, g_w1l);
    cudaGetSymbolAddress((void**)&w2h, g_w2h);
    cudaGetSymbolAddress((void**)&w2l, g_w2l);
    cudaGetSymbolAddress((void**)&woh, g_woh);
    cudaGetSymbolAddress((void**)&wol, g_wol);

    // Splits: x (big, HBM-bound) + weights (small)
    {
        int nv = (M_ * D_) / 4;
        split_kernel<<<2048, 256>>>(x, xh, xl, nv);
        nv = (H_ * HALF_) / 4;
        split_kernel<<<(nv + 255) / 256, 256>>>(w1, w1h, w1l, nv);
        split_kernel<<<(nv + 255) / 256, 256>>>(w2, w2h, w2l, nv);
        nv = (O_ * H_) / 4;
        split_kernel<<<(nv + 255) / 256, 256>>>(wo, woh, wol, nv);
    }

    dim3 g1(M_ / 128, H_ / 256);          // 512 x 2
    hmma_gemm1_kernel<<<g1, 512, SMEM_G1>>>();

    scan_kernel<<<BH_ / 256, 256>>>(b1, tau1, b2, tau2);

    hmma_gemm2_kernel<<<M_ / 128, 512, SMEM_G2>>>(bo, out);
}